// round 15
// baseline (speedup 1.0000x reference)
#include <cuda_runtime.h>
#include <cuda_fp16.h>
#include <cstdint>
#include <mma.h>
#include <math.h>

// Problem constants
#define D_MODEL   1024
#define NUM_HEADS 16
#define HEAD_DIM  64
#define SEQ       2048
#define BATCH     2
#define M_TOTAL   (BATCH * SEQ)   // 4096

// Scratch (no allocation allowed -> __device__ globals)
__device__ __half g_xh[M_TOTAL * D_MODEL];
__device__ __half g_wqh[D_MODEL * D_MODEL];
__device__ __half g_wkh[D_MODEL * D_MODEL];
__device__ __half g_wvh[D_MODEL * D_MODEL];
__device__ __half g_woh[D_MODEL * D_MODEL];
__device__ __half g_q[BATCH * NUM_HEADS * SEQ * HEAD_DIM];   // [B,H,S,Dh]
__device__ __half g_k[BATCH * NUM_HEADS * SEQ * HEAD_DIM];
__device__ __half g_v[BATCH * NUM_HEADS * SEQ * HEAD_DIM];
__device__ __half g_ctx[M_TOTAL * D_MODEL];                  // [B,S,D]

// ---------------------------------------------------------------------------
// helpers
// ---------------------------------------------------------------------------
__device__ __forceinline__ void cp_async16(void* smem_ptr, const void* gmem_ptr) {
    unsigned int s = (unsigned int)__cvta_generic_to_shared(smem_ptr);
    asm volatile("cp.async.cg.shared.global [%0], [%1], 16;\n" :: "r"(s), "l"(gmem_ptr));
}
__device__ __forceinline__ void cp_commit() { asm volatile("cp.async.commit_group;\n"); }
__device__ __forceinline__ void cp_wait0()  { asm volatile("cp.async.wait_group 0;\n"); }
__device__ __forceinline__ void cp_wait1()  { asm volatile("cp.async.wait_group 1;\n"); }

__device__ __forceinline__ unsigned smem_u32(const void* p) {
    return (unsigned)__cvta_generic_to_shared(p);
}

__device__ __forceinline__ void ldsm4(uint32_t& r0, uint32_t& r1, uint32_t& r2, uint32_t& r3,
                                      unsigned a) {
    asm volatile("ldmatrix.sync.aligned.m8n8.x4.shared.b16 {%0,%1,%2,%3}, [%4];"
                 : "=r"(r0), "=r"(r1), "=r"(r2), "=r"(r3) : "r"(a));
}
__device__ __forceinline__ void ldsm4t(uint32_t& r0, uint32_t& r1, uint32_t& r2, uint32_t& r3,
                                       unsigned a) {
    asm volatile("ldmatrix.sync.aligned.m8n8.x4.trans.shared.b16 {%0,%1,%2,%3}, [%4];"
                 : "=r"(r0), "=r"(r1), "=r"(r2), "=r"(r3) : "r"(a));
}
__device__ __forceinline__ void mma_16816(float c[4], const uint32_t a[4], const uint32_t b[2]) {
    asm volatile(
        "mma.sync.aligned.m16n8k16.row.col.f32.f16.f16.f32 "
        "{%0,%1,%2,%3}, {%4,%5,%6,%7}, {%8,%9}, {%0,%1,%2,%3};"
        : "+f"(c[0]), "+f"(c[1]), "+f"(c[2]), "+f"(c[3])
        : "r"(a[0]), "r"(a[1]), "r"(a[2]), "r"(a[3]), "r"(b[0]), "r"(b[1]));
}
__device__ __forceinline__ uint32_t h2pack(float x, float y) {
    __half2 h = __floats2half2_rn(x, y);
    return *reinterpret_cast<uint32_t*>(&h);
}

// ---------------------------------------------------------------------------
// float -> half conversions (one-time, DRAM streaming)
// ---------------------------------------------------------------------------
__global__ void __launch_bounds__(256)
f2h_kernel(const float* __restrict__ src, __half* __restrict__ dst)
{
    int i = (blockIdx.x * 256 + threadIdx.x) * 4;
    float4 v = *reinterpret_cast<const float4*>(src + i);
    *reinterpret_cast<__half2*>(dst + i)     = __floats2half2_rn(v.x, v.y);
    *reinterpret_cast<__half2*>(dst + i + 2) = __floats2half2_rn(v.z, v.w);
}

__global__ void __launch_bounds__(256)
w2h_kernel(const float* __restrict__ wq, const float* __restrict__ wk,
           const float* __restrict__ wv, const float* __restrict__ wo)
{
    const float* src;
    __half* dst;
    switch (blockIdx.y) {
        case 0:  src = wq; dst = g_wqh; break;
        case 1:  src = wk; dst = g_wkh; break;
        case 2:  src = wv; dst = g_wvh; break;
        default: src = wo; dst = g_woh; break;
    }
    int i = (blockIdx.x * 256 + threadIdx.x) * 4;
    float4 v = *reinterpret_cast<const float4*>(src + i);
    *reinterpret_cast<__half2*>(dst + i)     = __floats2half2_rn(v.x, v.y);
    *reinterpret_cast<__half2*>(dst + i + 2) = __floats2half2_rn(v.z, v.w);
}

// ---------------------------------------------------------------------------
// Raw mma.sync fp16 GEMM:  Y = X @ W^T
// CTA tile 128x128, K-stage 64, 3-stage cp.async ring, ONE barrier per stage.
// 8 warps: warp tile 32x64; c[2][8] m16n8 accum. Epilogue direct from regs.
// ---------------------------------------------------------------------------
#define BKH 64
#define HS  72   // padded half stride
#define GEMM_STAGE_HALFS (2 * 128 * HS)
#define GEMM_SMEM (3 * GEMM_STAGE_HALFS * 2)   // 110592 B

template <int MODE>
__global__ void __launch_bounds__(256, 2)
gemm_h(float* __restrict__ Yout, const float* __restrict__ bias)
{
    extern __shared__ __align__(16) char smraw[];
    __half* sm_h = (__half*)smraw;

    const __half* Xp;
    const __half* W;
    __half* Yh = nullptr;
    if (MODE == 0) {
        int which = blockIdx.z;
        W  = (which == 0) ? g_wqh : (which == 1) ? g_wkh : g_wvh;
        Yh = (which == 0) ? g_q   : (which == 1) ? g_k   : g_v;
        Xp = g_xh;
    } else {
        W  = g_woh;
        Xp = g_ctx;
    }

    const int m0 = blockIdx.y * 128;
    const int n0 = blockIdx.x * 128;
    const int tid  = threadIdx.x;
    const int warp = tid >> 5;
    const int lane = tid & 31;
    const int wm = warp >> 1;          // 0..3 : 32 rows each
    const int wn = warp & 1;           // 0..1 : 64 cols each
    const int lr = lane >> 2;          // tile row 0..7
    const int lc = (lane & 3) * 2;     // tile col pair base

    float c[2][8][4];
#pragma unroll
    for (int i = 0; i < 2; i++)
#pragma unroll
        for (int j = 0; j < 8; j++)
#pragma unroll
            for (int t = 0; t < 4; t++) c[i][j][t] = 0.0f;

    const int NIT = D_MODEL / BKH;   // 16

    auto load_stage = [&](int kblk, int s) {
        const int k0 = kblk * BKH;
        __half* Ab = sm_h + s * GEMM_STAGE_HALFS;
        __half* Bb = Ab + 128 * HS;
#pragma unroll
        for (int j = 0; j < 4; j++) {
            int idx = tid + j * 256;
            int row = idx >> 3;
            int ch  = idx & 7;
            cp_async16(Ab + row * HS + ch * 8,
                       Xp + (size_t)(m0 + row) * D_MODEL + k0 + ch * 8);
            cp_async16(Bb + row * HS + ch * 8,
                       W  + (size_t)(n0 + row) * D_MODEL + k0 + ch * 8);
        }
        cp_commit();
    };

    // prologue: stages 0 and 1 in flight
    load_stage(0, 0);
    load_stage(1, 1);

    // ldmatrix lane addressing (validated patterns)
    const int arow = (lane & 7) + ((lane >> 3) & 1) * 8;
    const int acol = (lane >> 4) * 8;
    const int brow = (lane & 7) + (lane >> 4) * 8;
    const int bcol = ((lane >> 3) & 1) * 8;

    for (int it = 0; it < NIT; it++) {
        if (it < NIT - 1) cp_wait1(); else cp_wait0();   // stage it complete
        __syncthreads();                                 // visible; buf (it-1)%3 free
        if (it + 2 < NIT) load_stage(it + 2, (it + 2) % 3);

        const unsigned Ab = smem_u32(sm_h + (it % 3) * GEMM_STAGE_HALFS);
        const unsigned Bb = Ab + 128 * HS * 2;
#pragma unroll
        for (int kt = 0; kt < 4; kt++) {
            uint32_t Aa[2][4];
#pragma unroll
            for (int i = 0; i < 2; i++)
                ldsm4(Aa[i][0], Aa[i][1], Aa[i][2], Aa[i][3],
                      Ab + (unsigned)((wm * 32 + i * 16 + arow) * HS + kt * 16 + acol) * 2);
            uint32_t KB[16];
#pragma unroll
            for (int g = 0; g < 4; g++)
                ldsm4(KB[g * 4], KB[g * 4 + 1], KB[g * 4 + 2], KB[g * 4 + 3],
                      Bb + (unsigned)((wn * 64 + g * 16 + brow) * HS + kt * 16 + bcol) * 2);
#pragma unroll
            for (int i = 0; i < 2; i++)
#pragma unroll
                for (int j = 0; j < 8; j++)
                    mma_16816(c[i][j], Aa[i], &KB[j * 2]);
        }
    }

    // ---- epilogue: direct from registers (no smem reads -> no barrier) ----
#pragma unroll
    for (int i = 0; i < 2; i++) {
        const int row0 = m0 + wm * 32 + i * 16 + lr;
        const int row1 = row0 + 8;
#pragma unroll
        for (int j = 0; j < 8; j++) {
            const int n = n0 + wn * 64 + j * 8 + lc;
            if (MODE == 0) {
                const int h = n >> 6;
                const int d = n & 63;
                const int b0 = row0 >> 11, s0 = row0 & 2047;
                const int b1 = row1 >> 11, s1 = row1 & 2047;
                *reinterpret_cast<__half2*>(
                    Yh + ((size_t)(b0 * NUM_HEADS + h) * SEQ + s0) * HEAD_DIM + d) =
                    __floats2half2_rn(c[i][j][0], c[i][j][1]);
                *reinterpret_cast<__half2*>(
                    Yh + ((size_t)(b1 * NUM_HEADS + h) * SEQ + s1) * HEAD_DIM + d) =
                    __floats2half2_rn(c[i][j][2], c[i][j][3]);
            } else {
                float2 bb = *reinterpret_cast<const float2*>(bias + n);
                float2 o0 = make_float2(c[i][j][0] + bb.x, c[i][j][1] + bb.y);
                float2 o1 = make_float2(c[i][j][2] + bb.x, c[i][j][3] + bb.y);
                *reinterpret_cast<float2*>(Yout + (size_t)row0 * D_MODEL + n) = o0;
                *reinterpret_cast<float2*>(Yout + (size_t)row1 * D_MODEL + n) = o1;
            }
        }
    }
}

// ---------------------------------------------------------------------------
// Fused causal flash attention (R13 2-stage) + base-2 softmax.
// Q prescaled by 0.125*log2(e); all exps are exp2f (single MUFU, no FMUL).
// smem: Qs h[128][72] @0 (18432) | Ks h[2][64][72] @18432 | Vs h[2][64][72] @36864
#define ATTN_SMEM 55296

__global__ void __launch_bounds__(256, 2)
attn_kernel()
{
    extern __shared__ __align__(16) char smraw[];
    __half* Qs = (__half*)smraw;
    __half* Ks = (__half*)(smraw + 18432);
    __half* Vs = (__half*)(smraw + 36864);

    const int qb = gridDim.x - 1 - blockIdx.x;   // long CTAs first
    const int bh = blockIdx.y;
    const __half* Q = g_q + (size_t)bh * SEQ * HEAD_DIM;
    const __half* K = g_k + (size_t)bh * SEQ * HEAD_DIM;
    const __half* V = g_v + (size_t)bh * SEQ * HEAD_DIM;
    const int q0 = qb * 128;
    const int NKB = 2 * qb + 2;

    const int tid  = threadIdx.x;
    const int warp = tid >> 5;
    const int lane = tid & 31;
    const int lr   = lane >> 2;
    const int lc   = (lane & 3) * 2;

    auto load_q = [&]() {
#pragma unroll
        for (int j = 0; j < 4; j++) {
            int idx = tid + j * 256;
            int row = idx >> 3;
            int ch  = idx & 7;
            cp_async16(Qs + row * HS + ch * 8, Q + (size_t)(q0 + row) * HEAD_DIM + ch * 8);
        }
        cp_commit();
    };
    auto load_kv = [&](int kb, int s) {
        __half* Kb = Ks + s * 64 * HS;
        __half* Vb = Vs + s * 64 * HS;
#pragma unroll
        for (int j = 0; j < 2; j++) {
            int idx = tid + j * 256;
            int row = idx >> 3;
            int ch  = idx & 7;
            cp_async16(Kb + row * HS + ch * 8, K + (size_t)(kb * 64 + row) * HEAD_DIM + ch * 8);
            cp_async16(Vb + row * HS + ch * 8, V + (size_t)(kb * 64 + row) * HEAD_DIM + ch * 8);
        }
        cp_commit();
    };

    load_q();
    load_kv(0, 0);
    cp_wait0();
    __syncthreads();

    // Q A-fragments register-resident; pre-scaled by 0.125*log2(e) so that
    // S is directly the base-2 softmax argument.
    uint32_t Qa[4][4];
    {
        const unsigned qbase = smem_u32(Qs);
        const int row = warp * 16 + (lane & 7) + ((lane >> 3) & 1) * 8;
        const int csel = (lane >> 4) * 8;
        const __half2 sc = __float2half2_rn(0.18033688f);   // 0.125 * log2(e)
#pragma unroll
        for (int kt = 0; kt < 4; kt++) {
            ldsm4(Qa[kt][0], Qa[kt][1], Qa[kt][2], Qa[kt][3],
                  qbase + (unsigned)(row * HS + kt * 16 + csel) * 2);
#pragma unroll
            for (int r = 0; r < 4; r++) {
                __half2 v = *reinterpret_cast<__half2*>(&Qa[kt][r]);
                v = __hmul2(v, sc);
                Qa[kt][r] = *reinterpret_cast<uint32_t*>(&v);
            }
        }
    }

    float O[8][4];
#pragma unroll
    for (int nt = 0; nt < 8; nt++)
#pragma unroll
        for (int i = 0; i < 4; i++) O[nt][i] = 0.0f;
    float m0 = -INFINITY, m1 = -INFINITY, l0 = 0.0f, l1 = 0.0f;
    const int qi0 = q0 + warp * 16 + lr;
    const int qi1 = qi0 + 8;
    const int qmin = q0 + warp * 16;
    const int qmax = qmin + 15;

    for (int kb = 0; kb < NKB; kb++) {
        const int buf = kb & 1;
        if (kb + 1 < NKB) load_kv(kb + 1, buf ^ 1);

        const __half* Kb = Ks + buf * 64 * HS;
        const __half* Vb = Vs + buf * 64 * HS;
        const int kbase = kb * 64;

        if (kbase <= qmax) {
            // ---- S = Q @ K^T (base-2 softmax argument) ----
            float S[8][4];
#pragma unroll
            for (int nt = 0; nt < 8; nt++)
#pragma unroll
                for (int i = 0; i < 4; i++) S[nt][i] = 0.0f;
            {
                const unsigned kb_s = smem_u32(Kb);
                const int krow = (lane & 7) + (lane >> 4) * 8;
                const int kcol = ((lane >> 3) & 1) * 8;
#pragma unroll
                for (int kt = 0; kt < 4; kt++) {
                    uint32_t KB[16];
#pragma unroll
                    for (int g = 0; g < 4; g++)
                        ldsm4(KB[g * 4], KB[g * 4 + 1], KB[g * 4 + 2], KB[g * 4 + 3],
                              kb_s + (unsigned)((g * 16 + krow) * HS + kt * 16 + kcol) * 2);
#pragma unroll
                    for (int nt = 0; nt < 8; nt++)
                        mma_16816(S[nt], Qa[kt], &KB[nt * 2]);
                }
            }

            // ---- online softmax (base 2) on registers ----
            float mx0 = -INFINITY, mx1 = -INFINITY;
            if (kbase + 63 > qmin) {
#pragma unroll
                for (int nt = 0; nt < 8; nt++) {
                    const int c0 = kbase + nt * 8 + lc;
                    float x0 = (c0     <= qi0) ? S[nt][0] : -INFINITY;
                    float x1 = (c0 + 1 <= qi0) ? S[nt][1] : -INFINITY;
                    float x2 = (c0     <= qi1) ? S[nt][2] : -INFINITY;
                    float x3 = (c0 + 1 <= qi1) ? S[nt][3] : -INFINITY;
                    S[nt][0] = x0; S[nt][1] = x1; S[nt][2] = x2; S[nt][3] = x3;
                    mx0 = fmaxf(mx0, fmaxf(x0, x1));
                    mx1 = fmaxf(mx1, fmaxf(x2, x3));
                }
            } else {
#pragma unroll
                for (int nt = 0; nt < 8; nt++) {
                    mx0 = fmaxf(mx0, fmaxf(S[nt][0], S[nt][1]));
                    mx1 = fmaxf(mx1, fmaxf(S[nt][2], S[nt][3]));
                }
            }
            mx0 = fmaxf(mx0, __shfl_xor_sync(0xFFFFFFFFu, mx0, 1));
            mx0 = fmaxf(mx0, __shfl_xor_sync(0xFFFFFFFFu, mx0, 2));
            mx1 = fmaxf(mx1, __shfl_xor_sync(0xFFFFFFFFu, mx1, 1));
            mx1 = fmaxf(mx1, __shfl_xor_sync(0xFFFFFFFFu, mx1, 2));
            const float mn0 = fmaxf(m0, mx0);
            const float mn1 = fmaxf(m1, mx1);
            const float corr0 = exp2f(m0 - mn0);
            const float corr1 = exp2f(m1 - mn1);

            // P (half) packed directly as A-fragments for PV
            uint32_t Pa[4][4];
            float s0 = 0.0f, s1 = 0.0f;
#pragma unroll
            for (int kt = 0; kt < 4; kt++) {
                float p00 = exp2f(S[2 * kt][0] - mn0);
                float p01 = exp2f(S[2 * kt][1] - mn0);
                float p02 = exp2f(S[2 * kt][2] - mn1);
                float p03 = exp2f(S[2 * kt][3] - mn1);
                float p10 = exp2f(S[2 * kt + 1][0] - mn0);
                float p11 = exp2f(S[2 * kt + 1][1] - mn0);
                float p12 = exp2f(S[2 * kt + 1][2] - mn1);
                float p13 = exp2f(S[2 * kt + 1][3] - mn1);
                Pa[kt][0] = h2pack(p00, p01);
                Pa[kt][1] = h2pack(p02, p03);
                Pa[kt][2] = h2pack(p10, p11);
                Pa[kt][3] = h2pack(p12, p13);
                s0 += p00 + p01 + p10 + p11;
                s1 += p02 + p03 + p12 + p13;
            }
            s0 += __shfl_xor_sync(0xFFFFFFFFu, s0, 1);
            s0 += __shfl_xor_sync(0xFFFFFFFFu, s0, 2);
            s1 += __shfl_xor_sync(0xFFFFFFFFu, s1, 1);
            s1 += __shfl_xor_sync(0xFFFFFFFFu, s1, 2);
            l0 = l0 * corr0 + s0;
            l1 = l1 * corr1 + s1;
            m0 = mn0; m1 = mn1;

            // ---- O rescale + PV ----
#pragma unroll
            for (int nt = 0; nt < 8; nt++) {
                O[nt][0] *= corr0; O[nt][1] *= corr0;
                O[nt][2] *= corr1; O[nt][3] *= corr1;
            }
            {
                const unsigned vb_s = smem_u32(Vb);
                const int vrow = (lane & 7) + ((lane >> 3) & 1) * 8;
                const int vcol = (lane >> 4) * 8;
#pragma unroll
                for (int kt = 0; kt < 4; kt++) {
                    uint32_t VB[16];
#pragma unroll
                    for (int g = 0; g < 4; g++)
                        ldsm4t(VB[g * 4], VB[g * 4 + 1], VB[g * 4 + 2], VB[g * 4 + 3],
                               vb_s + (unsigned)((kt * 16 + vrow) * HS + g * 16 + vcol) * 2);
#pragma unroll
                    for (int nt = 0; nt < 8; nt++)
                        mma_16816(O[nt], Pa[kt], &VB[nt * 2]);
                }
            }
        }

        if (kb + 1 < NKB) cp_wait0();
        __syncthreads();
    }

    // ---- finalize: ctx[b, s, h*64 + d] (half) ----
    {
        const float inv0 = 1.0f / l0;
        const float inv1 = 1.0f / l1;
        const int b = bh / NUM_HEADS;
        const int h = bh % NUM_HEADS;
        __half* o0 = g_ctx + (size_t)(b * SEQ + qi0) * D_MODEL + h * HEAD_DIM + lc;
        __half* o1 = g_ctx + (size_t)(b * SEQ + qi1) * D_MODEL + h * HEAD_DIM + lc;
#pragma unroll
        for (int nt = 0; nt < 8; nt++) {
            *reinterpret_cast<__half2*>(o0 + nt * 8) =
                __floats2half2_rn(O[nt][0] * inv0, O[nt][1] * inv0);
            *reinterpret_cast<__half2*>(o1 + nt * 8) =
                __floats2half2_rn(O[nt][2] * inv1, O[nt][3] * inv1);
        }
    }
}

// ---------------------------------------------------------------------------
// launch
// ---------------------------------------------------------------------------
extern "C" void kernel_launch(void* const* d_in, const int* in_sizes, int n_in,
                              void* d_out, int out_size)
{
    const float* x  = (const float*)d_in[0];
    const float* wq = (const float*)d_in[1];
    const float* wk = (const float*)d_in[2];
    const float* wv = (const float*)d_in[3];
    const float* wo = (const float*)d_in[4];
    const float* bo = (const float*)d_in[5];
    float* out = (float*)d_out;

    cudaFuncSetAttribute(gemm_h<0>, cudaFuncAttributeMaxDynamicSharedMemorySize, GEMM_SMEM);
    cudaFuncSetAttribute(gemm_h<1>, cudaFuncAttributeMaxDynamicSharedMemorySize, GEMM_SMEM);
    cudaFuncSetAttribute(attn_kernel, cudaFuncAttributeMaxDynamicSharedMemorySize, ATTN_SMEM);

    __half* xh;
    cudaGetSymbolAddress((void**)&xh, g_xh);

    f2h_kernel<<<(M_TOTAL * D_MODEL) / 1024, 256>>>(x, xh);
    dim3 gw((D_MODEL * D_MODEL) / 1024, 4);
    w2h_kernel<<<gw, 256>>>(wq, wk, wv, wo);

    dim3 gqkv(D_MODEL / 128, M_TOTAL / 128, 3);
    gemm_h<0><<<gqkv, 256, GEMM_SMEM>>>(nullptr, nullptr);

    dim3 gattn(SEQ / 128, BATCH * NUM_HEADS);
    attn_kernel<<<gattn, 256, ATTN_SMEM>>>();

    dim3 gout(D_MODEL / 128, M_TOTAL / 128, 1);
    gemm_h<1><<<gout, 256, GEMM_SMEM>>>(out, bo);
}

// round 17
// speedup vs baseline: 1.0388x; 1.0388x over previous
#include <cuda_runtime.h>
#include <cuda_fp16.h>
#include <cstdint>
#include <mma.h>
#include <math.h>

// Problem constants
#define D_MODEL   1024
#define NUM_HEADS 16
#define HEAD_DIM  64
#define SEQ       2048
#define BATCH     2
#define M_TOTAL   (BATCH * SEQ)   // 4096

// Scratch (no allocation allowed -> __device__ globals)
__device__ __half g_xh[M_TOTAL * D_MODEL];
__device__ __half g_wqh[D_MODEL * D_MODEL];
__device__ __half g_wkh[D_MODEL * D_MODEL];
__device__ __half g_wvh[D_MODEL * D_MODEL];
__device__ __half g_woh[D_MODEL * D_MODEL];
__device__ __half g_q[BATCH * NUM_HEADS * SEQ * HEAD_DIM];   // [B,H,S,Dh]
__device__ __half g_k[BATCH * NUM_HEADS * SEQ * HEAD_DIM];
__device__ __half g_v[BATCH * NUM_HEADS * SEQ * HEAD_DIM];
__device__ __half g_ctx[M_TOTAL * D_MODEL];                  // [B,S,D]

// ---------------------------------------------------------------------------
// helpers
// ---------------------------------------------------------------------------
__device__ __forceinline__ void cp_async16(void* smem_ptr, const void* gmem_ptr) {
    unsigned int s = (unsigned int)__cvta_generic_to_shared(smem_ptr);
    asm volatile("cp.async.cg.shared.global [%0], [%1], 16;\n" :: "r"(s), "l"(gmem_ptr));
}
__device__ __forceinline__ void cp_commit() { asm volatile("cp.async.commit_group;\n"); }
__device__ __forceinline__ void cp_wait0()  { asm volatile("cp.async.wait_group 0;\n"); }
__device__ __forceinline__ void cp_wait1()  { asm volatile("cp.async.wait_group 1;\n"); }

__device__ __forceinline__ unsigned smem_u32(const void* p) {
    return (unsigned)__cvta_generic_to_shared(p);
}

__device__ __forceinline__ void ldsm4(uint32_t& r0, uint32_t& r1, uint32_t& r2, uint32_t& r3,
                                      unsigned a) {
    asm volatile("ldmatrix.sync.aligned.m8n8.x4.shared.b16 {%0,%1,%2,%3}, [%4];"
                 : "=r"(r0), "=r"(r1), "=r"(r2), "=r"(r3) : "r"(a));
}
__device__ __forceinline__ void ldsm4t(uint32_t& r0, uint32_t& r1, uint32_t& r2, uint32_t& r3,
                                       unsigned a) {
    asm volatile("ldmatrix.sync.aligned.m8n8.x4.trans.shared.b16 {%0,%1,%2,%3}, [%4];"
                 : "=r"(r0), "=r"(r1), "=r"(r2), "=r"(r3) : "r"(a));
}
__device__ __forceinline__ void ldsm2t(uint32_t& r0, uint32_t& r1, unsigned a) {
    asm volatile("ldmatrix.sync.aligned.m8n8.x2.trans.shared.b16 {%0,%1}, [%2];"
                 : "=r"(r0), "=r"(r1) : "r"(a));
}
__device__ __forceinline__ void mma_16816(float c[4], const uint32_t a[4], const uint32_t b[2]) {
    asm volatile(
        "mma.sync.aligned.m16n8k16.row.col.f32.f16.f16.f32 "
        "{%0,%1,%2,%3}, {%4,%5,%6,%7}, {%8,%9}, {%0,%1,%2,%3};"
        : "+f"(c[0]), "+f"(c[1]), "+f"(c[2]), "+f"(c[3])
        : "r"(a[0]), "r"(a[1]), "r"(a[2]), "r"(a[3]), "r"(b[0]), "r"(b[1]));
}
__device__ __forceinline__ uint32_t h2pack(float x, float y) {
    __half2 h = __floats2half2_rn(x, y);
    return *reinterpret_cast<uint32_t*>(&h);
}
__device__ __forceinline__ uint32_t ex2_h2(uint32_t a) {
    uint32_t d;
    asm("ex2.approx.f16x2 %0, %1;" : "=r"(d) : "r"(a));
    return d;
}

// ---------------------------------------------------------------------------
// fused float -> half conversion (one launch): y 0..3 = x quarters, 4..7 = weights
// ---------------------------------------------------------------------------
__global__ void __launch_bounds__(256)
conv_kernel(const float* __restrict__ x,  const float* __restrict__ wq,
            const float* __restrict__ wk, const float* __restrict__ wv,
            const float* __restrict__ wo)
{
    const float* src;
    __half* dst;
    switch (blockIdx.y) {
        case 0:  src = x;             dst = g_xh;             break;
        case 1:  src = x + 1048576;   dst = g_xh + 1048576;   break;
        case 2:  src = x + 2097152;   dst = g_xh + 2097152;   break;
        case 3:  src = x + 3145728;   dst = g_xh + 3145728;   break;
        case 4:  src = wq; dst = g_wqh; break;
        case 5:  src = wk; dst = g_wkh; break;
        case 6:  src = wv; dst = g_wvh; break;
        default: src = wo; dst = g_woh; break;
    }
    int i = (blockIdx.x * 256 + threadIdx.x) * 4;
    float4 v = *reinterpret_cast<const float4*>(src + i);
    *reinterpret_cast<__half2*>(dst + i)     = __floats2half2_rn(v.x, v.y);
    *reinterpret_cast<__half2*>(dst + i + 2) = __floats2half2_rn(v.z, v.w);
}

// ---------------------------------------------------------------------------
// Raw mma.sync fp16 GEMM (unchanged R15): 128x128x64 tiles, 3-stage ring.
// ---------------------------------------------------------------------------
#define BKH 64
#define HS  72   // padded half stride
#define GEMM_STAGE_HALFS (2 * 128 * HS)
#define GEMM_SMEM (3 * GEMM_STAGE_HALFS * 2)   // 110592 B

template <int MODE>
__global__ void __launch_bounds__(256, 2)
gemm_h(float* __restrict__ Yout, const float* __restrict__ bias)
{
    extern __shared__ __align__(16) char smraw[];
    __half* sm_h = (__half*)smraw;

    const __half* Xp;
    const __half* W;
    __half* Yh = nullptr;
    if (MODE == 0) {
        int which = blockIdx.z;
        W  = (which == 0) ? g_wqh : (which == 1) ? g_wkh : g_wvh;
        Yh = (which == 0) ? g_q   : (which == 1) ? g_k   : g_v;
        Xp = g_xh;
    } else {
        W  = g_woh;
        Xp = g_ctx;
    }

    const int m0 = blockIdx.y * 128;
    const int n0 = blockIdx.x * 128;
    const int tid  = threadIdx.x;
    const int warp = tid >> 5;
    const int lane = tid & 31;
    const int wm = warp >> 1;
    const int wn = warp & 1;
    const int lr = lane >> 2;
    const int lc = (lane & 3) * 2;

    float c[2][8][4];
#pragma unroll
    for (int i = 0; i < 2; i++)
#pragma unroll
        for (int j = 0; j < 8; j++)
#pragma unroll
            for (int t = 0; t < 4; t++) c[i][j][t] = 0.0f;

    const int NIT = D_MODEL / BKH;   // 16

    auto load_stage = [&](int kblk, int s) {
        const int k0 = kblk * BKH;
        __half* Ab = sm_h + s * GEMM_STAGE_HALFS;
        __half* Bb = Ab + 128 * HS;
#pragma unroll
        for (int j = 0; j < 4; j++) {
            int idx = tid + j * 256;
            int row = idx >> 3;
            int ch  = idx & 7;
            cp_async16(Ab + row * HS + ch * 8,
                       Xp + (size_t)(m0 + row) * D_MODEL + k0 + ch * 8);
            cp_async16(Bb + row * HS + ch * 8,
                       W  + (size_t)(n0 + row) * D_MODEL + k0 + ch * 8);
        }
        cp_commit();
    };

    load_stage(0, 0);
    load_stage(1, 1);

    const int arow = (lane & 7) + ((lane >> 3) & 1) * 8;
    const int acol = (lane >> 4) * 8;
    const int brow = (lane & 7) + (lane >> 4) * 8;
    const int bcol = ((lane >> 3) & 1) * 8;

    for (int it = 0; it < NIT; it++) {
        if (it < NIT - 1) cp_wait1(); else cp_wait0();
        __syncthreads();
        if (it + 2 < NIT) load_stage(it + 2, (it + 2) % 3);

        const unsigned Ab = smem_u32(sm_h + (it % 3) * GEMM_STAGE_HALFS);
        const unsigned Bb = Ab + 128 * HS * 2;
#pragma unroll
        for (int kt = 0; kt < 4; kt++) {
            uint32_t Aa[2][4];
#pragma unroll
            for (int i = 0; i < 2; i++)
                ldsm4(Aa[i][0], Aa[i][1], Aa[i][2], Aa[i][3],
                      Ab + (unsigned)((wm * 32 + i * 16 + arow) * HS + kt * 16 + acol) * 2);
            uint32_t KB[16];
#pragma unroll
            for (int g = 0; g < 4; g++)
                ldsm4(KB[g * 4], KB[g * 4 + 1], KB[g * 4 + 2], KB[g * 4 + 3],
                      Bb + (unsigned)((wn * 64 + g * 16 + brow) * HS + kt * 16 + bcol) * 2);
#pragma unroll
            for (int i = 0; i < 2; i++)
#pragma unroll
                for (int j = 0; j < 8; j++)
                    mma_16816(c[i][j], Aa[i], &KB[j * 2]);
        }
    }

#pragma unroll
    for (int i = 0; i < 2; i++) {
        const int row0 = m0 + wm * 32 + i * 16 + lr;
        const int row1 = row0 + 8;
#pragma unroll
        for (int j = 0; j < 8; j++) {
            const int n = n0 + wn * 64 + j * 8 + lc;
            if (MODE == 0) {
                const int h = n >> 6;
                const int d = n & 63;
                const int b0 = row0 >> 11, s0 = row0 & 2047;
                const int b1 = row1 >> 11, s1 = row1 & 2047;
                *reinterpret_cast<__half2*>(
                    Yh + ((size_t)(b0 * NUM_HEADS + h) * SEQ + s0) * HEAD_DIM + d) =
                    __floats2half2_rn(c[i][j][0], c[i][j][1]);
                *reinterpret_cast<__half2*>(
                    Yh + ((size_t)(b1 * NUM_HEADS + h) * SEQ + s1) * HEAD_DIM + d) =
                    __floats2half2_rn(c[i][j][2], c[i][j][3]);
            } else {
                float2 bb = *reinterpret_cast<const float2*>(bias + n);
                float2 o0 = make_float2(c[i][j][0] + bb.x, c[i][j][1] + bb.y);
                float2 o1 = make_float2(c[i][j][2] + bb.x, c[i][j][3] + bb.y);
                *reinterpret_cast<float2*>(Yout + (size_t)row0 * D_MODEL + n) = o0;
                *reinterpret_cast<float2*>(Yout + (size_t)row1 * D_MODEL + n) = o1;
            }
        }
    }
}

// ---------------------------------------------------------------------------
// Fused causal flash attention: register pipeline, base-2 softmax,
// f16x2 exp, and l accumulated via ones-column MMA (V padding col 64 = 1).
// smem: Qs h[128][72] @0 | Ks h[2][64][72] @18432 | Vs h[2][64][72] @36864
#define ATTN_SMEM 55296

__global__ void __launch_bounds__(256, 2)
attn_kernel()
{
    extern __shared__ __align__(16) char smraw[];
    __half* Qs = (__half*)smraw;
    __half* Ks = (__half*)(smraw + 18432);
    __half* Vs = (__half*)(smraw + 36864);

    const int qb = gridDim.x - 1 - blockIdx.x;   // long CTAs first
    const int bh = blockIdx.y;
    const __half* Q = g_q + (size_t)bh * SEQ * HEAD_DIM;
    const __half* K = g_k + (size_t)bh * SEQ * HEAD_DIM;
    const __half* V = g_v + (size_t)bh * SEQ * HEAD_DIM;
    const int q0 = qb * 128;
    const int NKB = 2 * qb + 2;

    const int tid  = threadIdx.x;
    const int warp = tid >> 5;
    const int lane = tid & 31;
    const int lr   = lane >> 2;
    const int lc   = (lane & 3) * 2;

    auto load_q = [&]() {
#pragma unroll
        for (int j = 0; j < 4; j++) {
            int idx = tid + j * 256;
            int row = idx >> 3;
            int ch  = idx & 7;
            cp_async16(Qs + row * HS + ch * 8, Q + (size_t)(q0 + row) * HEAD_DIM + ch * 8);
        }
        cp_commit();
    };
    auto load_kv = [&](int kb, int s) {
        __half* Kb = Ks + s * 64 * HS;
        __half* Vb = Vs + s * 64 * HS;
#pragma unroll
        for (int j = 0; j < 2; j++) {
            int idx = tid + j * 256;
            int row = idx >> 3;
            int ch  = idx & 7;
            cp_async16(Kb + row * HS + ch * 8, K + (size_t)(kb * 64 + row) * HEAD_DIM + ch * 8);
            cp_async16(Vb + row * HS + ch * 8, V + (size_t)(kb * 64 + row) * HEAD_DIM + ch * 8);
        }
        cp_commit();
    };

    load_q();
    load_kv(0, 0);

    // Ones column in V padding: Vs[*][64] = 1.0h, [65..71] = 0 (both buffers,
    // written once; the KV loader only touches cols 0..63).
    if (tid < 128) {
        __half* p = Vs + tid * HS + 64;
        *reinterpret_cast<uint4*>(p) = make_uint4(0x00003C00u, 0u, 0u, 0u);
    }

    cp_wait0();
    __syncthreads();

    // Q A-fragments register-resident; pre-scaled by 0.125*log2(e) for base-2 softmax.
    uint32_t Qa[4][4];
    {
        const unsigned qbase = smem_u32(Qs);
        const int row = warp * 16 + (lane & 7) + ((lane >> 3) & 1) * 8;
        const int csel = (lane >> 4) * 8;
        const __half2 sc = __float2half2_rn(0.18033688f);   // 0.125 * log2(e)
#pragma unroll
        for (int kt = 0; kt < 4; kt++) {
            ldsm4(Qa[kt][0], Qa[kt][1], Qa[kt][2], Qa[kt][3],
                  qbase + (unsigned)(row * HS + kt * 16 + csel) * 2);
#pragma unroll
            for (int r = 0; r < 4; r++) {
                __half2 v = *reinterpret_cast<__half2*>(&Qa[kt][r]);
                v = __hmul2(v, sc);
                Qa[kt][r] = *reinterpret_cast<uint32_t*>(&v);
            }
        }
    }

    float O[8][4];
#pragma unroll
    for (int nt = 0; nt < 8; nt++)
#pragma unroll
        for (int i = 0; i < 4; i++) O[nt][i] = 0.0f;
    float Ol[4] = {0.0f, 0.0f, 0.0f, 0.0f};   // ones-column accumulator (l)
    float m0 = -INFINITY, m1 = -INFINITY;
    const int qi0 = q0 + warp * 16 + lr;
    const int qi1 = qi0 + 8;
    const int qmin = q0 + warp * 16;
    const int qmax = qmin + 15;

    for (int kb = 0; kb < NKB; kb++) {
        const int buf = kb & 1;
        if (kb + 1 < NKB) load_kv(kb + 1, buf ^ 1);

        const __half* Kb = Ks + buf * 64 * HS;
        const __half* Vb = Vs + buf * 64 * HS;
        const int kbase = kb * 64;

        if (kbase <= qmax) {
            // ---- S = Q @ K^T ----
            float S[8][4];
#pragma unroll
            for (int nt = 0; nt < 8; nt++)
#pragma unroll
                for (int i = 0; i < 4; i++) S[nt][i] = 0.0f;
            {
                const unsigned kb_s = smem_u32(Kb);
                const int krow = (lane & 7) + (lane >> 4) * 8;
                const int kcol = ((lane >> 3) & 1) * 8;
#pragma unroll
                for (int kt = 0; kt < 4; kt++) {
                    uint32_t KB[16];
#pragma unroll
                    for (int g = 0; g < 4; g++)
                        ldsm4(KB[g * 4], KB[g * 4 + 1], KB[g * 4 + 2], KB[g * 4 + 3],
                              kb_s + (unsigned)((g * 16 + krow) * HS + kt * 16 + kcol) * 2);
#pragma unroll
                    for (int nt = 0; nt < 8; nt++)
                        mma_16816(S[nt], Qa[kt], &KB[nt * 2]);
                }
            }

            // ---- max + mask (base-2 softmax argument already in S) ----
            float mx0 = -INFINITY, mx1 = -INFINITY;
            if (kbase + 63 > qmin) {
#pragma unroll
                for (int nt = 0; nt < 8; nt++) {
                    const int c0 = kbase + nt * 8 + lc;
                    float x0 = (c0     <= qi0) ? S[nt][0] : -INFINITY;
                    float x1 = (c0 + 1 <= qi0) ? S[nt][1] : -INFINITY;
                    float x2 = (c0     <= qi1) ? S[nt][2] : -INFINITY;
                    float x3 = (c0 + 1 <= qi1) ? S[nt][3] : -INFINITY;
                    S[nt][0] = x0; S[nt][1] = x1; S[nt][2] = x2; S[nt][3] = x3;
                    mx0 = fmaxf(mx0, fmaxf(x0, x1));
                    mx1 = fmaxf(mx1, fmaxf(x2, x3));
                }
            } else {
#pragma unroll
                for (int nt = 0; nt < 8; nt++) {
                    mx0 = fmaxf(mx0, fmaxf(S[nt][0], S[nt][1]));
                    mx1 = fmaxf(mx1, fmaxf(S[nt][2], S[nt][3]));
                }
            }
            mx0 = fmaxf(mx0, __shfl_xor_sync(0xFFFFFFFFu, mx0, 1));
            mx0 = fmaxf(mx0, __shfl_xor_sync(0xFFFFFFFFu, mx0, 2));
            mx1 = fmaxf(mx1, __shfl_xor_sync(0xFFFFFFFFu, mx1, 1));
            mx1 = fmaxf(mx1, __shfl_xor_sync(0xFFFFFFFFu, mx1, 2));
            const float mn0 = fmaxf(m0, mx0);
            const float mn1 = fmaxf(m1, mx1);
            const float corr0 = exp2f(m0 - mn0);
            const float corr1 = exp2f(m1 - mn1);
            m0 = mn0; m1 = mn1;

            // ---- P = exp2(S - m) via f16x2 (packed directly as A-fragments) ----
            uint32_t Pa[4][4];
#pragma unroll
            for (int kt = 0; kt < 4; kt++) {
                Pa[kt][0] = ex2_h2(h2pack(S[2 * kt][0] - mn0,     S[2 * kt][1] - mn0));
                Pa[kt][1] = ex2_h2(h2pack(S[2 * kt][2] - mn1,     S[2 * kt][3] - mn1));
                Pa[kt][2] = ex2_h2(h2pack(S[2 * kt + 1][0] - mn0, S[2 * kt + 1][1] - mn0));
                Pa[kt][3] = ex2_h2(h2pack(S[2 * kt + 1][2] - mn1, S[2 * kt + 1][3] - mn1));
            }

            // ---- O (and Ol) rescale + PV (+ ones column) ----
#pragma unroll
            for (int nt = 0; nt < 8; nt++) {
                O[nt][0] *= corr0; O[nt][1] *= corr0;
                O[nt][2] *= corr1; O[nt][3] *= corr1;
            }
            Ol[0] *= corr0; Ol[1] *= corr0; Ol[2] *= corr1; Ol[3] *= corr1;
            {
                const unsigned vb_s = smem_u32(Vb);
                const int vrow = (lane & 7) + ((lane >> 3) & 1) * 8;
                const int vcol = (lane >> 4) * 8;
#pragma unroll
                for (int kt = 0; kt < 4; kt++) {
                    uint32_t VB[16];
#pragma unroll
                    for (int g = 0; g < 4; g++)
                        ldsm4t(VB[g * 4], VB[g * 4 + 1], VB[g * 4 + 2], VB[g * 4 + 3],
                               vb_s + (unsigned)((kt * 16 + vrow) * HS + g * 16 + vcol) * 2);
                    uint32_t vb1[2];
                    ldsm2t(vb1[0], vb1[1],
                           vb_s + (unsigned)((kt * 16 + (lane & 15)) * HS + 64) * 2);
#pragma unroll
                    for (int nt = 0; nt < 8; nt++)
                        mma_16816(O[nt], Pa[kt], &VB[nt * 2]);
                    mma_16816(Ol, Pa[kt], vb1);
                }
            }
        }

        if (kb + 1 < NKB) cp_wait0();
        __syncthreads();
    }

    // ---- finalize: l lives in the ones column (lanes with lc==0) ----
    {
        const float l0 = __shfl_sync(0xFFFFFFFFu, Ol[0], lane & ~3);
        const float l1 = __shfl_sync(0xFFFFFFFFu, Ol[2], lane & ~3);
        const float inv0 = 1.0f / l0;
        const float inv1 = 1.0f / l1;
        const int b = bh / NUM_HEADS;
        const int h = bh % NUM_HEADS;
        __half* o0 = g_ctx + (size_t)(b * SEQ + qi0) * D_MODEL + h * HEAD_DIM + lc;
        __half* o1 = g_ctx + (size_t)(b * SEQ + qi1) * D_MODEL + h * HEAD_DIM + lc;
#pragma unroll
        for (int nt = 0; nt < 8; nt++) {
            *reinterpret_cast<__half2*>(o0 + nt * 8) =
                __floats2half2_rn(O[nt][0] * inv0, O[nt][1] * inv0);
            *reinterpret_cast<__half2*>(o1 + nt * 8) =
                __floats2half2_rn(O[nt][2] * inv1, O[nt][3] * inv1);
        }
    }
}

// ---------------------------------------------------------------------------
// launch
// ---------------------------------------------------------------------------
extern "C" void kernel_launch(void* const* d_in, const int* in_sizes, int n_in,
                              void* d_out, int out_size)
{
    const float* x  = (const float*)d_in[0];
    const float* wq = (const float*)d_in[1];
    const float* wk = (const float*)d_in[2];
    const float* wv = (const float*)d_in[3];
    const float* wo = (const float*)d_in[4];
    const float* bo = (const float*)d_in[5];
    float* out = (float*)d_out;

    cudaFuncSetAttribute(gemm_h<0>, cudaFuncAttributeMaxDynamicSharedMemorySize, GEMM_SMEM);
    cudaFuncSetAttribute(gemm_h<1>, cudaFuncAttributeMaxDynamicSharedMemorySize, GEMM_SMEM);
    cudaFuncSetAttribute(attn_kernel, cudaFuncAttributeMaxDynamicSharedMemorySize, ATTN_SMEM);

    // fused fp32 -> fp16 converts (x + all 4 weights) in one launch
    dim3 gconv((D_MODEL * D_MODEL) / 1024, 8);
    conv_kernel<<<gconv, 256>>>(x, wq, wk, wv, wo);

    dim3 gqkv(D_MODEL / 128, M_TOTAL / 128, 3);
    gemm_h<0><<<gqkv, 256, GEMM_SMEM>>>(nullptr, nullptr);

    dim3 gattn(SEQ / 128, BATCH * NUM_HEADS);
    attn_kernel<<<gattn, 256, ATTN_SMEM>>>();

    dim3 gout(D_MODEL / 128, M_TOTAL / 128, 1);
    gemm_h<1><<<gout, 256, GEMM_SMEM>>>(out, bo);
}